// round 6
// baseline (speedup 1.0000x reference)
#include <cuda_runtime.h>
#include <math.h>

#define PI_F 3.14159f

// Fixed problem shape: B=4, D=C=256, H=W=64, P=256
#define Bsz 4
#define Dd  256
#define Hh  64
#define Ww  64
#define Pp  256

#define NMLP   32                       // 8 chunks x 4 batches
#define NGRID  (NMLP + Bsz * Dd)        // 1056 CTAs

// Scratch / per-(b,d) transform parameters
__device__ float g_p[Bsz * Pp];
__device__ float g_scale[Bsz * Dd];
__device__ float g_cos[Bsz * Dd];
__device__ float g_sin[Bsz * Dd];
__device__ float g_t0[Bsz * Dd];
__device__ float g_t1[Bsz * Dd];

// Cross-CTA sync state (zero-initialized at load; reset by last CTA each run)
__device__ int g_cnt1[Bsz];
__device__ int g_cnt2[Bsz];
__device__ int g_done;

// Sampler shared-plane geometry
#define PAD    2
#define PITCH  69                        // odd pitch (bank-friendly)
#define PROWS  (Hh + 2 * PAD)            // 68
#define NHALO  (2 * 2 * PITCH + Hh * 5)  // rows 0,1,66,67 full + 5 side cells/row

__global__ void __launch_bounds__(256, 6) fused_kernel(
        const float* __restrict__ vol,
        const float* __restrict__ para,
        const float* __restrict__ W_c, const float* __restrict__ b_c,
        const float* __restrict__ W_s, const float* __restrict__ b_s,
        const float* __restrict__ W_r, const float* __restrict__ b_r,
        const float* __restrict__ W_t, const float* __restrict__ b_t,
        float* __restrict__ out) {
    __shared__ float2 sh[PROWS * PITCH];   // 37536 B; MLP path reuses as scratch

    const int bid = blockIdx.x;
    const int tid = threadIdx.x;

    if (bid < NMLP) {
        // ================= MLP path =================
        float* shf = (float*)sh;
        // layout: spara/sp at [0..255], partials at [256..]
        const int chunk = bid & 7;
        const int b     = bid >> 3;
        const int tc    = tid & 31;
        const int j     = tid >> 5;           // k-split 0..7
        const int t     = chunk * 32 + tc;    // global output column

        // ---- stage 1: p = relu(para @ W_c + b_c), this chunk's 32 columns
        shf[tid] = para[b * Pp + tid];
        __syncthreads();

        {
            float acc = 0.0f;
            const int k0 = j * 32;
#pragma unroll 8
            for (int kk = 0; kk < 32; ++kk) {
                const int k = k0 + kk;
                acc = fmaf(shf[k], W_c[k * Pp + t], acc);
            }
            shf[256 + j * 32 + tc] = acc;
        }
        __syncthreads();

        if (tid < 32) {
            float v = b_c[chunk * 32 + tid];
#pragma unroll
            for (int jj = 0; jj < 8; ++jj) v += shf[256 + jj * 32 + tid];
            g_p[b * Pp + chunk * 32 + tid] = fmaxf(v, 0.0f);
        }
        __syncthreads();
        if (tid == 0) {
            __threadfence();
            atomicAdd(&g_cnt1[b], 1);
            // wait for all 8 chunks of this batch
            while (*((volatile int*)&g_cnt1[b]) < 8) __nanosleep(32);
        }
        __syncthreads();

        // ---- stage 2: four heads for this chunk's 32 columns
        shf[tid] = __ldcg(&g_p[b * Pp + tid]);
        __syncthreads();

        {
            float as = 0.0f, ar = 0.0f, at0 = 0.0f, at1 = 0.0f;
            const int k0 = j * 32;
            const float2* __restrict__ W_t2 = (const float2*)W_t;
#pragma unroll 4
            for (int kk = 0; kk < 32; ++kk) {
                const int k = k0 + kk;
                const float pk = shf[k];
                as  = fmaf(pk, W_s[k * Pp + t], as);
                ar  = fmaf(pk, W_r[k * Pp + t], ar);
                const float2 wt = W_t2[k * Pp + t];
                at0 = fmaf(pk, wt.x, at0);
                at1 = fmaf(pk, wt.y, at1);
            }
            float* p2 = shf + 256;               // part2[8][32][4]
            p2[(j * 32 + tc) * 4 + 0] = as;
            p2[(j * 32 + tc) * 4 + 1] = ar;
            p2[(j * 32 + tc) * 4 + 2] = at0;
            p2[(j * 32 + tc) * 4 + 3] = at1;
        }
        __syncthreads();

        if (tid < 32) {
            const int tg = chunk * 32 + tid;
            float vs = b_s[tg];
            float vr = b_r[tg];
            float v0 = b_t[2 * tg];
            float v1 = b_t[2 * tg + 1];
            const float* p2 = shf + 256;
#pragma unroll
            for (int jj = 0; jj < 8; ++jj) {
                vs += p2[(jj * 32 + tid) * 4 + 0];
                vr += p2[(jj * 32 + tid) * 4 + 1];
                v0 += p2[(jj * 32 + tid) * 4 + 2];
                v1 += p2[(jj * 32 + tid) * 4 + 3];
            }
            const float scale = 2.0f / (1.0f + expf(-vs));
            const float angle = tanhf(vr) * PI_F;

            const int idx = b * Dd + tg;
            g_scale[idx] = scale;
            g_cos[idx]   = cosf(angle);
            g_sin[idx]   = sinf(angle);
            g_t0[idx]    = tanhf(v0);
            g_t1[idx]    = tanhf(v1);
        }
        __syncthreads();
        if (tid == 0) {
            __threadfence();
            atomicAdd(&g_cnt2[b], 1);
        }
    } else {
        // ================= sample path =================
        const int bd = bid - NMLP;
        const int b  = bd >> 8;
        const int d  = bd & 255;

        // z -> iz (reference op order) — no params needed yet
        const float gz  = 2.0f * ((float)d / (float)(Dd - 1)) - 1.0f;
        const float iz  = ((gz + 1.0f) * (float)Dd - 1.0f) * 0.5f;
        const float z0f = floorf(iz);
        const float wz1 = iz - z0f;
        const float wz0 = 1.0f - wz1;
        const int   z0  = (int)z0f;

        const float* base = vol + (size_t)b * Dd * Hh * Ww;
        const bool z0ok = (z0 >= 0) && (z0 < Dd);
        const bool z1ok = (z0 + 1 >= 0) && (z0 + 1 < Dd);
        const float4* p0v = (const float4*)(base + (size_t)(z0ok ? z0 : 0) * (Hh * Ww));
        const float4* p1v = (const float4*)(base + (size_t)(z1ok ? z0 + 1 : 0) * (Hh * Ww));
        const float4 zero4 = make_float4(0.f, 0.f, 0.f, 0.f);

        // halo zeroing + interior fill (one phase)
        for (int i = tid; i < NHALO; i += 256) {
            int row, col;
            if (i < 4 * PITCH) {
                const int r = i / PITCH;
                row = (r < 2) ? r : (Hh + r);
                col = i - r * PITCH;
            } else {
                const int m = i - 4 * PITCH;
                row = 2 + m / 5;
                const int cc = m - (m / 5) * 5;
                col = (cc < 2) ? cc : (Hh + cc);
            }
            sh[row * PITCH + col] = make_float2(0.f, 0.f);
        }
#pragma unroll
        for (int jj = 0; jj < 4; ++jj) {
            const int g  = tid + jj * 256;
            const int y  = g >> 4;
            const int x4 = (g & 15) << 2;
            const float4 a  = z0ok ? p0v[g] : zero4;
            const float4 bb = z1ok ? p1v[g] : zero4;
            float2* dst = &sh[(y + PAD) * PITCH + (x4 + PAD)];
            dst[0] = make_float2(a.x, bb.x);
            dst[1] = make_float2(a.y, bb.y);
            dst[2] = make_float2(a.z, bb.z);
            dst[3] = make_float2(a.w, bb.w);
        }

        // wait for this batch's params (set by wave-1-resident MLP CTAs)
        if (tid == 0) {
            while (*((volatile int*)&g_cnt2[b]) < 8) __nanosleep(32);
        }
        __syncthreads();   // also covers the smem fill above

        const float sc = __ldcg(&g_scale[bd]);
        const float c  = __ldcg(&g_cos[bd]);
        const float s  = __ldcg(&g_sin[bd]);
        const float t0 = __ldcg(&g_t0[bd]);
        const float t1 = __ldcg(&g_t1[bd]);

        // px constant per thread; py = py0 + 4k  ->  ix, iy affine in k
        const int px  = tid & 63;
        const int py0 = tid >> 6;

        const float gx  = fmaf((float)px,  2.0f / 63.0f, -1.0f);
        const float gy0 = fmaf((float)py0, 2.0f / 63.0f, -1.0f);
        const float dgy = 4.0f * (2.0f / 63.0f);

        const float tx0 = (c * gx - s * gy0) * sc + t0;
        const float ty0 = (s * gx + c * gy0) * sc + t1;
        const float ix0 = fmaf(tx0, 32.0f, 31.5f);
        const float iy0 = fmaf(ty0, 32.0f, 31.5f);
        const float dix = -s * sc * dgy * 32.0f;
        const float diy =  c * sc * dgy * 32.0f;

        float* outp = out + (size_t)bd * (Hh * Ww) + py0 * Ww + px;

#pragma unroll 4
        for (int k = 0; k < 16; ++k) {
            const float kf = (float)k;
            const float ix = fmaf(kf, dix, ix0);
            const float iy = fmaf(kf, diy, iy0);

            const float xf = floorf(ix);
            const float yf = floorf(iy);
            const float wx = ix - xf;
            const float wy = iy - yf;

            int x0 = (int)xf;
            int y0 = (int)yf;
            x0 = max(-PAD, min(x0, Ww));            // OOB taps land in zero halo
            y0 = max(-PAD, min(y0, Hh));

            const float2* q = &sh[(y0 + PAD) * PITCH + (x0 + PAD)];
            const float2 v00 = q[0];
            const float2 v01 = q[1];
            const float2 v10 = q[PITCH];
            const float2 v11 = q[PITCH + 1];

            const float t00 = fmaf(v00.x, wz0, v00.y * wz1);
            const float t01 = fmaf(v01.x, wz0, v01.y * wz1);
            const float t10 = fmaf(v10.x, wz0, v10.y * wz1);
            const float t11 = fmaf(v11.x, wz0, v11.y * wz1);

            const float h0 = fmaf(t01 - t00, wx, t00);
            const float h1 = fmaf(t11 - t10, wx, t10);
            outp[k * 4 * Ww] = fmaf(h1 - h0, wy, h0);
        }
    }

    // ---- epilogue: last CTA resets sync state for the next graph replay ----
    __syncthreads();
    if (tid == 0) {
        const int v = atomicAdd(&g_done, 1);
        if (v == NGRID - 1) {
#pragma unroll
            for (int i = 0; i < Bsz; ++i) { g_cnt1[i] = 0; g_cnt2[i] = 0; }
            __threadfence();
            g_done = 0;
        }
    }
}

extern "C" void kernel_launch(void* const* d_in, const int* in_sizes, int n_in,
                              void* d_out, int out_size) {
    const float* feature_map = (const float*)d_in[0];
    const float* para_code   = (const float*)d_in[1];
    const float* W_c = (const float*)d_in[2];
    const float* b_c = (const float*)d_in[3];
    const float* W_s = (const float*)d_in[4];
    const float* b_s = (const float*)d_in[5];
    const float* W_r = (const float*)d_in[6];
    const float* b_r = (const float*)d_in[7];
    const float* W_t = (const float*)d_in[8];
    const float* b_t = (const float*)d_in[9];
    float* out = (float*)d_out;

    fused_kernel<<<NGRID, 256>>>(feature_map, para_code,
                                 W_c, b_c, W_s, b_s, W_r, b_r, W_t, b_t, out);
}